// round 2
// baseline (speedup 1.0000x reference)
#include <cuda_runtime.h>
#include <cuda_bf16.h>
#include <cstdint>

// BatchRankingLoss: G=511 groups of d=256 decoys.
// loss = sum_{g,i,j} w_ij * max(0, 1 + y_ij*(o_i - o_j)) / (G*d*(d-1))
//   y_ij = -1 if (t_i - t_j) < 0 else +1 ;  w_ij = |t_i - t_j| > 0.1
//
// Symmetry: term(i,j) == term(j,i)  (y and do both negate; dt==0 is weighted
// out), so full sum = 2 * sum over unordered pairs.
// Pair enumeration, per thread i: j = (i+m) mod 256 for m=1..127 covers each
// unordered pair exactly once; m=128 covers each distance-128 pair twice, so
// it gets weight 0.5. Every thread runs exactly 129 uniform iterations
// (m=0 diagonal included for a clean 128-long unrolled loop; it contributes 0).
//
// Single kernel: per-group sums -> global scratch, last CTA (ticket counter)
// reduces and writes d_out. Counter is reset by the last CTA -> graph-replay
// deterministic.

#define DECOYS 256
#define THRESH 0.1f

__device__ float    g_group_sums[4096];
__device__ unsigned g_ticket;   // zero-initialized; reset each call by last CTA

__device__ __forceinline__ float pair_term(float oi, float ti, float2 v)
{
    const float dt = ti - v.y;
    const float dd = oi - v.x;
    // y*do via sign-bit xor (y = -1 iff dt < 0; dt==-0.0 is weighted out)
    const uint32_t s_bits =
        __float_as_uint(dd) ^ (__float_as_uint(dt) & 0x80000000u);
    const float term = fmaxf(0.0f, 1.0f + __uint_as_float(s_bits));
    return (fabsf(dt) > THRESH) ? term : 0.0f;
}

__global__ __launch_bounds__(DECOYS) void ranking_loss_kernel(
    const float* __restrict__ o_in,   // [B,1] -> [B]
    const float* __restrict__ t_in,   // [B]
    float* __restrict__ out,
    int G)
{
    __shared__ float2 ot[DECOYS];
    __shared__ float  wsum[DECOYS / 32];
    __shared__ bool   is_last;

    const int g    = blockIdx.x;
    const int i    = threadIdx.x;
    const int base = g * DECOYS;

    const float oi = o_in[base + i];
    const float ti = t_in[base + i];
    ot[i] = make_float2(oi, ti);
    __syncthreads();

    float acc = 0.0f;
    int   j   = i;                     // m=0 start (diagonal, contributes 0)
#pragma unroll 8
    for (int m = 0; m < 128; ++m) {    // m = 0..127
        const float2 v = ot[j];        // broadcast-free scattered LDS.64
        acc += pair_term(oi, ti, v);   // predicated FADD in SASS
        j = (j + 1) & (DECOYS - 1);
    }
    // m = 128: each distance-128 pair computed by both endpoints -> half weight
    acc += 0.5f * pair_term(oi, ti, ot[j]);

    // warp + CTA reduce
#pragma unroll
    for (int off = 16; off > 0; off >>= 1)
        acc += __shfl_xor_sync(0xffffffffu, acc, off);
    if ((i & 31) == 0) wsum[i >> 5] = acc;
    __syncthreads();

    if (i == 0) {
        float s = 0.0f;
#pragma unroll
        for (int w = 0; w < DECOYS / 32; ++w) s += wsum[w];
        g_group_sums[g] = s;
        __threadfence();
        unsigned old = atomicAdd(&g_ticket, 1u);
        is_last = (old == (unsigned)(G - 1));
    }
    __syncthreads();

    if (is_last) {
        __threadfence();               // acquire the other CTAs' sums
        float v = g_group_sums[i];
        if (i + DECOYS < G) v += g_group_sums[i + DECOYS];

#pragma unroll
        for (int off = 16; off > 0; off >>= 1)
            v += __shfl_xor_sync(0xffffffffu, v, off);
        if ((i & 31) == 0) wsum[i >> 5] = v;
        __syncthreads();

        if (i == 0) {
            float s = 0.0f;
#pragma unroll
            for (int w = 0; w < DECOYS / 32; ++w) s += wsum[w];
            const float inv_n =
                1.0f / ((float)G * (float)DECOYS * (float)(DECOYS - 1));
            out[0] = 2.0f * s * inv_n;   // x2: unordered -> ordered pairs
            g_ticket = 0;                // reset for next graph replay
        }
    }
}

extern "C" void kernel_launch(void* const* d_in, const int* in_sizes, int n_in,
                              void* d_out, int out_size)
{
    const float* o = (const float*)d_in[0];  // input  [B,1] f32
    const float* t = (const float*)d_in[1];  // gdt_ts [B]   f32
    float* out = (float*)d_out;

    const int B = in_sizes[1];
    const int K = B / DECOYS;       // 512
    const int G = K - 1;            // 511 (reference skips final group)

    ranking_loss_kernel<<<G, DECOYS>>>(o, t, out, G);
}

// round 3
// speedup vs baseline: 1.6642x; 1.6642x over previous
#include <cuda_runtime.h>
#include <cuda_bf16.h>
#include <cstdint>

// BatchRankingLoss: G=511 groups of d=256 decoys.
// loss = sum_{g,i,j} w_ij * max(0, 1 + y_ij*(o_i - o_j)) / (G*d*(d-1))
//   y_ij = -1 if (t_i - t_j) < 0 else +1 ;  w_ij = |t_i - t_j| > 0.1
//
// Symmetry: term(i,j) == term(j,i), so full sum = 2 * sum over unordered pairs.
// Enumeration: per thread i, j = i+m for m=1..127 covers each unordered pair
// once; m=128 covers each distance-128 pair twice -> half weight. The shared
// (o,t) array is PADDED to 384 entries (first 128 duplicated) so j=i+m never
// wraps: after unrolling every LDS.64 is [Rbase + immediate] with zero
// per-iteration index arithmetic (this was the R2 regression).
//
// Fused reduction: per-group sums -> scratch; last CTA (ticket counter)
// reduces and writes d_out. Ticket reset by last CTA -> replay-deterministic.

#define DECOYS 256
#define PAD    (DECOYS + DECOYS / 2)   // 384
#define THRESH 0.1f

__device__ float    g_group_sums[4096];
__device__ unsigned g_ticket;   // zero-init; reset each call by last CTA

__device__ __forceinline__ float pair_term(float oi, float ti, float2 v)
{
    const float dt = ti - v.y;
    const float dd = oi - v.x;
    // y*do via sign-bit xor (y = -1 iff dt < 0; dt==-0.0 is weighted out)
    const uint32_t s_bits =
        __float_as_uint(dd) ^ (__float_as_uint(dt) & 0x80000000u);
    const float term = fmaxf(0.0f, 1.0f + __uint_as_float(s_bits));
    return (fabsf(dt) > THRESH) ? term : 0.0f;
}

__global__ __launch_bounds__(DECOYS) void ranking_loss_kernel(
    const float* __restrict__ o_in,   // [B,1] -> [B]
    const float* __restrict__ t_in,   // [B]
    float* __restrict__ out,
    int G)
{
    __shared__ float2 ot[PAD];
    __shared__ float  wsum[DECOYS / 32];
    __shared__ bool   is_last;

    const int g    = blockIdx.x;
    const int i    = threadIdx.x;
    const int base = g * DECOYS;

    const float oi = o_in[base + i];
    const float ti = t_in[base + i];
    const float2 my = make_float2(oi, ti);
    ot[i] = my;
    if (i < PAD - DECOYS) ot[DECOYS + i] = my;   // duplicate first 128 rows
    __syncthreads();

    const float2* row = &ot[i];   // all inner accesses: row[m], m compile-time
    float acc0 = 0.0f, acc1 = 0.0f;
#pragma unroll 16
    for (int m = 1; m < 128; m += 2) {           // m = 1..127 (63.5 pairs/thr)
        acc0 += pair_term(oi, ti, row[m]);
        acc1 += pair_term(oi, ti, row[m + 1]);   // m+1 = 128 on last iter
    }
    // m=128 was counted at full weight in the loop above (last m+1), but each
    // distance-128 pair is generated by BOTH endpoints -> subtract half of it.
    acc1 -= 0.5f * pair_term(oi, ti, row[128]);

    float acc = acc0 + acc1;

    // warp + CTA reduce
#pragma unroll
    for (int off = 16; off > 0; off >>= 1)
        acc += __shfl_xor_sync(0xffffffffu, acc, off);
    if ((i & 31) == 0) wsum[i >> 5] = acc;
    __syncthreads();

    if (i == 0) {
        float s = 0.0f;
#pragma unroll
        for (int w = 0; w < DECOYS / 32; ++w) s += wsum[w];
        g_group_sums[g] = s;
        __threadfence();
        unsigned old = atomicAdd(&g_ticket, 1u);
        is_last = (old == (unsigned)(G - 1));
    }
    __syncthreads();

    if (is_last) {
        __threadfence();               // acquire other CTAs' sums
        float v = g_group_sums[i];
        if (i + DECOYS < G) v += g_group_sums[i + DECOYS];

#pragma unroll
        for (int off = 16; off > 0; off >>= 1)
            v += __shfl_xor_sync(0xffffffffu, v, off);
        if ((i & 31) == 0) wsum[i >> 5] = v;
        __syncthreads();

        if (i == 0) {
            float s = 0.0f;
#pragma unroll
            for (int w = 0; w < DECOYS / 32; ++w) s += wsum[w];
            const float inv_n =
                1.0f / ((float)G * (float)DECOYS * (float)(DECOYS - 1));
            out[0] = 2.0f * s * inv_n;   // x2: unordered -> ordered pairs
            g_ticket = 0;                // reset for next graph replay
        }
    }
}

extern "C" void kernel_launch(void* const* d_in, const int* in_sizes, int n_in,
                              void* d_out, int out_size)
{
    const float* o = (const float*)d_in[0];  // input  [B,1] f32
    const float* t = (const float*)d_in[1];  // gdt_ts [B]   f32
    float* out = (float*)d_out;

    const int B = in_sizes[1];
    const int K = B / DECOYS;       // 512
    const int G = K - 1;            // 511 (reference skips final group)

    ranking_loss_kernel<<<G, DECOYS>>>(o, t, out, G);
}